// round 7
// baseline (speedup 1.0000x reference)
#include <cuda_runtime.h>
#include <math.h>

// NTM shapes
#define Bb 256
#define Tt 128
#define Ii 512
#define Hh 512
#define Nn 1024
#define Mm 512
#define Oo 512
#define NBLK 148
#define NTHR 512
#define BH (Bb * Hh)
#define BM (Bb * Mm)

typedef unsigned long long ull;

// ---------------- persistent state / scratch (device globals) ---------------
__device__ float g_mem[Nn * Mm];
__device__ float g_wr[Bb * Nn];
__device__ float g_ww[Bb * Nn];
__device__ float g_h[Bb * Hh];
__device__ float g_ea[Bb * 2 * Mm];
__device__ float g_rpart[4 * Bb * Mm];
__device__ float g_hpart[4 * Bb * Hh];
__device__ float g_pw[Bb * (Mm + 6)];
__device__ float g_pr[Bb * (Mm + 6)];
__device__ float g_scw[Bb * 8];
__device__ float g_scr[Bb * 8];
__device__ float g_simw[Bb * Nn];
__device__ float g_simr[Bb * Nn];
__device__ float g_invmem[Nn];
__device__ unsigned g_bar_count;
__device__ unsigned g_bar_gen;

// ---------------- grid barrier ----------------------------------------------
static __device__ __forceinline__ void gridBarrier() {
    __syncthreads();
    __threadfence();
    if (threadIdx.x == 0) {
        unsigned gen = *(volatile unsigned*)&g_bar_gen;
        unsigned prev = atomicAdd(&g_bar_count, 1u);
        if (prev == NBLK - 1) {
            g_bar_count = 0;
            __threadfence();
            *(volatile unsigned*)&g_bar_gen = gen + 1;
        } else {
            while (*(volatile unsigned*)&g_bar_gen == gen) { __nanosleep(64); }
        }
    }
    __syncthreads();
}

// ---------------- packed f32x2 helpers ---------------------------------------
static __device__ __forceinline__ void fmax2(ull &d, ull a, ull b) {
    asm("fma.rn.f32x2 %0, %1, %2, %3;" : "=l"(d) : "l"(a), "l"(b), "l"(d));
}
static __device__ __forceinline__ float2 unpack2(ull v) {
    float2 f;
    asm("mov.b64 {%0, %1}, %2;" : "=f"(f.x), "=f"(f.y) : "l"(v));
    return f;
}
static __device__ __forceinline__ float psum(ull v) {
    float2 f = unpack2(v);
    return f.x + f.y;
}

// ---------------- math helpers ----------------------------------------------
static __device__ __forceinline__ float sigm(float x) { return 1.f / (1.f + __expf(-x)); }
static __device__ __forceinline__ float tanh_f(float x) {
    float t = __expf(-2.f * fabsf(x));
    float r = (1.f - t) / (1.f + t);
    return copysignf(r, x);
}
static __device__ __forceinline__ float softplus_(float x) {
    return fmaxf(x, 0.f) + log1pf(__expf(-fabsf(x)));
}
static __device__ __forceinline__ float warpReduceSum(float v) {
    #pragma unroll
    for (int o = 16; o > 0; o >>= 1) v += __shfl_xor_sync(0xffffffffu, v, o);
    return v;
}
static __device__ __forceinline__ float warpReduceMax(float v) {
    #pragma unroll
    for (int o = 16; o > 0; o >>= 1) v = fmaxf(v, __shfl_xor_sync(0xffffffffu, v, o));
    return v;
}
static __device__ __forceinline__ float blockReduceSum512(float v) {
    __shared__ float sh[16];
    int lane = threadIdx.x & 31, wid = threadIdx.x >> 5;
    v = warpReduceSum(v);
    if (lane == 0) sh[wid] = v;
    __syncthreads();
    if (wid == 0) {
        float t = (lane < 16) ? sh[lane] : 0.f;
        t = warpReduceSum(t);
        if (lane == 0) sh[0] = t;
    }
    __syncthreads();
    float r = sh[0];
    __syncthreads();
    return r;
}
static __device__ __forceinline__ float blockReduceMax512(float v) {
    __shared__ float sh[16];
    int lane = threadIdx.x & 31, wid = threadIdx.x >> 5;
    v = warpReduceMax(v);
    if (lane == 0) sh[wid] = v;
    __syncthreads();
    if (wid == 0) {
        float t = (lane < 16) ? sh[lane] : -3.4e38f;
        t = warpReduceMax(t);
        if (lane == 0) sh[0] = t;
    }
    __syncthreads();
    float r = sh[0];
    __syncthreads();
    return r;
}

// k-interleaved operand staging: per operand 2 bufs x 8 kkpairs x 68 ull
// buf stride = 544 ull = 1088 floats
#define OPB 544

// inner step: 2 row-pairs x 4 cols
#define FMA2x4(acc, a2, w0, w1, w2, w3)                               \
    {                                                                  \
        fmax2(acc[0][0], a2.x, w0); fmax2(acc[0][1], a2.x, w1);        \
        fmax2(acc[0][2], a2.x, w2); fmax2(acc[0][3], a2.x, w3);        \
        fmax2(acc[1][0], a2.y, w0); fmax2(acc[1][1], a2.y, w1);        \
        fmax2(acc[1][2], a2.y, w2); fmax2(acc[1][3], a2.y, w3);        \
    }

// ---------------- 64x64 NN GEMM tile: C = act(A@W + bias) --------------------
// act: 0 none, 2 sigmoid, 3 tanh col<512, 4 sigmoid col<512 | tanh col>=512.
// compute map: rows ty*2+{0,1} (ty=tid>>4), cols tx+{0,16,32,48} (tx=tid&15)
static __device__ __forceinline__ void gemm64_nn(
    const float* __restrict__ A, int lda,
    const float* __restrict__ W, int ldw,
    const float* __restrict__ bias,
    float* __restrict__ C, int ldc,
    int bm, int bn, int Nc, int K, int act, float* shb)
{
    ull* Au = (ull*)shb;
    ull* Wu = (ull*)shb + 2 * OPB;
    float* Af = (float*)Au;
    float* Wf = (float*)Wu;
    const int tid = threadIdx.x;
    const int tx = tid & 15, ty = tid >> 4;
    const int am = tid >> 4, ak = tid & 15;      // A loader: rows am, am+32
    const int wk = tid >> 6, wn = tid & 63;      // W loader: ks wk, wk+8
    const float* Ap = A + (size_t)(bm + am) * lda + ak;
    const float* Wp = W + (size_t)wk * ldw + bn + wn;
    const bool wok = (bn + wn) < Nc;
    const int ai0 = ((ak >> 1) * 68 + am) * 2 + (ak & 1);
    const int ai1 = ((ak >> 1) * 68 + am + 32) * 2 + (ak & 1);
    const int wi0 = ((wk >> 1) * 68 + wn) * 2 + (wk & 1);
    const int wi1 = ((4 + (wk >> 1)) * 68 + wn) * 2 + (wk & 1);

    ull acc[2][4] = {};
    float ra0 = Ap[0], ra1 = Ap[(size_t)32 * lda];
    float rw0 = wok ? Wp[0] : 0.f, rw1 = wok ? Wp[(size_t)8 * ldw] : 0.f;
    Af[ai0] = ra0; Af[ai1] = ra1;
    Wf[wi0] = rw0; Wf[wi1] = rw1;
    __syncthreads();
    int buf = 0;
    for (int k0 = 0; k0 < K; k0 += 16) {
        if (k0 + 16 < K) {
            ra0 = Ap[k0 + 16]; ra1 = Ap[(size_t)32 * lda + k0 + 16];
            const float* Wp2 = Wp + (size_t)(k0 + 16) * ldw;
            rw0 = wok ? Wp2[0] : 0.f; rw1 = wok ? Wp2[(size_t)8 * ldw] : 0.f;
        }
        const ull* Ab = Au + buf * OPB;
        const ull* Wb = Wu + buf * OPB;
        #pragma unroll
        for (int kp = 0; kp < 8; kp++) {
            ulonglong2 a2 = *(const ulonglong2*)(Ab + kp * 68 + ty * 2);
            ull w0 = Wb[kp * 68 + tx];
            ull w1 = Wb[kp * 68 + tx + 16];
            ull w2 = Wb[kp * 68 + tx + 32];
            ull w3 = Wb[kp * 68 + tx + 48];
            FMA2x4(acc, a2, w0, w1, w2, w3);
        }
        if (k0 + 16 < K) {
            __syncthreads();
            int nb = buf ^ 1;
            Af[nb * 1088 + ai0] = ra0; Af[nb * 1088 + ai1] = ra1;
            Wf[nb * 1088 + wi0] = rw0; Wf[nb * 1088 + wi1] = rw1;
            __syncthreads();
            buf = nb;
        }
    }
    __syncthreads();
    #pragma unroll
    for (int r = 0; r < 2; r++) {
        int row = bm + ty * 2 + r;
        #pragma unroll
        for (int j = 0; j < 4; j++) {
            int col = bn + tx + j * 16;
            if (col >= Nc) continue;
            float v = psum(acc[r][j]);
            if (bias) v += bias[col];
            if (act == 2) v = sigm(v);
            else if (act == 3) { if (col < 512) v = tanh_f(v); }
            else if (act == 4) { v = (col < 512) ? sigm(v) : tanh_f(v); }
            C[(size_t)row * ldc + col] = v;
        }
    }
}

// ---------------- 64x64 NT GEMM tile: C[b,n] = sum_k A[b,k]*Bm[n,k] ---------
static __device__ __forceinline__ void gemm64_nt(
    const float* __restrict__ A, int lda,
    const float* __restrict__ Bm, int ldb,
    float* __restrict__ C, int ldc,
    int bm, int bn, int K, float* shb)
{
    ull* Au = (ull*)shb;
    ull* Wu = (ull*)shb + 2 * OPB;
    float* Af = (float*)Au;
    float* Wf = (float*)Wu;
    const int tid = threadIdx.x;
    const int tx = tid & 15, ty = tid >> 4;
    const int am = tid >> 4, ak = tid & 15;
    const float* Ap = A + (size_t)(bm + am) * lda + ak;
    const float* Bp = Bm + (size_t)(bn + am) * ldb + ak;    // A-style loader (coalesced)
    const int ai0 = ((ak >> 1) * 68 + am) * 2 + (ak & 1);
    const int ai1 = ((ak >> 1) * 68 + am + 32) * 2 + (ak & 1);

    ull acc[2][4] = {};
    float ra0 = Ap[0], ra1 = Ap[(size_t)32 * lda];
    float rb0 = Bp[0], rb1 = Bp[(size_t)32 * ldb];
    Af[ai0] = ra0; Af[ai1] = ra1;
    Wf[ai0] = rb0; Wf[ai1] = rb1;
    __syncthreads();
    int buf = 0;
    for (int k0 = 0; k0 < K; k0 += 16) {
        if (k0 + 16 < K) {
            ra0 = Ap[k0 + 16]; ra1 = Ap[(size_t)32 * lda + k0 + 16];
            rb0 = Bp[k0 + 16]; rb1 = Bp[(size_t)32 * ldb + k0 + 16];
        }
        const ull* Ab = Au + buf * OPB;
        const ull* Wb = Wu + buf * OPB;
        #pragma unroll
        for (int kp = 0; kp < 8; kp++) {
            ulonglong2 a2 = *(const ulonglong2*)(Ab + kp * 68 + ty * 2);
            ull w0 = Wb[kp * 68 + tx];
            ull w1 = Wb[kp * 68 + tx + 16];
            ull w2 = Wb[kp * 68 + tx + 32];
            ull w3 = Wb[kp * 68 + tx + 48];
            FMA2x4(acc, a2, w0, w1, w2, w3);
        }
        if (k0 + 16 < K) {
            __syncthreads();
            int nb = buf ^ 1;
            Af[nb * 1088 + ai0] = ra0; Af[nb * 1088 + ai1] = ra1;
            Wf[nb * 1088 + ai0] = rb0; Wf[nb * 1088 + ai1] = rb1;
            __syncthreads();
            buf = nb;
        }
    }
    __syncthreads();
    #pragma unroll
    for (int r = 0; r < 2; r++) {
        int row = bm + ty * 2 + r;
        #pragma unroll
        for (int j = 0; j < 4; j++)
            C[(size_t)row * ldc + (bn + tx + j * 16)] = psum(acc[r][j]);
    }
}

// ---------------- mem update tile: mem = mem*(1 - ww^T e/B) + ww^T a/B ------
static __device__ __forceinline__ void memupd_tile(int tn, int tm, float* shb)
{
    ull* Nu = (ull*)shb;                  // ww (n-side, output rows)
    ull* Eu = (ull*)shb + 2 * OPB;
    ull* Aau = (ull*)shb + 4 * OPB;
    float* Nf = (float*)Nu;
    float* Ef = (float*)Eu;
    float* Aaf = (float*)Aau;
    const int bnrow = tn * 64, bmcol = tm * 64;
    const int tid = threadIdx.x;
    const int tx = tid & 15, ty = tid >> 4;
    const int wk = tid >> 6, wn = tid & 63;      // W-style loader for all 3 operands
    const float* wp = g_ww + (size_t)wk * Nn + bnrow + wn;
    const float* ep = g_ea + (size_t)wk * (2 * Mm) + bmcol + wn;
    const float* ap = ep + Mm;
    const int wi0 = ((wk >> 1) * 68 + wn) * 2 + (wk & 1);
    const int wi1 = ((4 + (wk >> 1)) * 68 + wn) * 2 + (wk & 1);

    ull acce[2][4] = {};
    ull acca[2][4] = {};
    float rw0 = wp[0], rw1 = wp[(size_t)8 * Nn];
    float re0 = ep[0], re1 = ep[(size_t)8 * (2 * Mm)];
    float rr0 = ap[0], rr1 = ap[(size_t)8 * (2 * Mm)];
    Nf[wi0] = rw0; Nf[wi1] = rw1;
    Ef[wi0] = re0; Ef[wi1] = re1;
    Aaf[wi0] = rr0; Aaf[wi1] = rr1;
    __syncthreads();
    int buf = 0;
    for (int b0 = 0; b0 < Bb; b0 += 16) {
        if (b0 + 16 < Bb) {
            const float* wp2 = wp + (size_t)(b0 + 16) * Nn;
            const float* ep2 = ep + (size_t)(b0 + 16) * (2 * Mm);
            const float* ap2 = ap + (size_t)(b0 + 16) * (2 * Mm);
            rw0 = wp2[0]; rw1 = wp2[(size_t)8 * Nn];
            re0 = ep2[0]; re1 = ep2[(size_t)8 * (2 * Mm)];
            rr0 = ap2[0]; rr1 = ap2[(size_t)8 * (2 * Mm)];
        }
        const ull* Nb = Nu + buf * OPB;
        const ull* Eb = Eu + buf * OPB;
        const ull* Ab = Aau + buf * OPB;
        #pragma unroll
        for (int kp = 0; kp < 8; kp++) {
            ulonglong2 n2 = *(const ulonglong2*)(Nb + kp * 68 + ty * 2);
            ull e0 = Eb[kp * 68 + tx],      e1 = Eb[kp * 68 + tx + 16];
            ull e2 = Eb[kp * 68 + tx + 32], e3 = Eb[kp * 68 + tx + 48];
            ull a0 = Ab[kp * 68 + tx],      a1 = Ab[kp * 68 + tx + 16];
            ull a2 = Ab[kp * 68 + tx + 32], a3 = Ab[kp * 68 + tx + 48];
            FMA2x4(acce, n2, e0, e1, e2, e3);
            FMA2x4(acca, n2, a0, a1, a2, a3);
        }
        if (b0 + 16 < Bb) {
            __syncthreads();
            int nb = buf ^ 1;
            Nf[nb * 1088 + wi0] = rw0; Nf[nb * 1088 + wi1] = rw1;
            Ef[nb * 1088 + wi0] = re0; Ef[nb * 1088 + wi1] = re1;
            Aaf[nb * 1088 + wi0] = rr0; Aaf[nb * 1088 + wi1] = rr1;
            __syncthreads();
            buf = nb;
        }
    }
    __syncthreads();
    const float invB = 1.f / (float)Bb;
    #pragma unroll
    for (int r = 0; r < 2; r++) {
        int n = bnrow + ty * 2 + r;
        #pragma unroll
        for (int j = 0; j < 4; j++) {
            int m = bmcol + tx + j * 16;
            float ev = psum(acce[r][j]);
            float av = psum(acca[r][j]);
            float old = g_mem[(size_t)n * Mm + m];
            g_mem[(size_t)n * Mm + m] = old * (1.f - ev * invB) + av * invB;
        }
    }
}

// ---------------- controller split-K tile ------------------------------------
// chunk c: 0,1 -> x halves; 2,3 -> r (= sum of 4 rpart) halves. K=256 each.
static __device__ __forceinline__ void gemmD_tile(
    int c, int bm, int bn, const float* __restrict__ xb,
    const float* __restrict__ Wx, const float* __restrict__ Wr, float* shb)
{
    ull* Au = (ull*)shb;
    ull* Wu = (ull*)shb + 2 * OPB;
    float* Af = (float*)Au;
    float* Wf = (float*)Wu;
    const int tid = threadIdx.x;
    const int tx = tid & 15, ty = tid >> 4;
    const int am = tid >> 4, ak = tid & 15;
    const int wk = tid >> 6, wn = tid & 63;
    const float* Wp = ((c < 2) ? (Wx + (size_t)c * 256 * Hh)
                               : (Wr + (size_t)(c - 2) * 256 * Hh))
                      + (size_t)wk * Hh + bn + wn;
    const float* Ax = xb + (size_t)(bm + am) * (Tt * Ii) + c * 256 + ak;
    const float* Ar = g_rpart + (size_t)(bm + am) * Mm + (c - 2) * 256 + ak;
    const int ai0 = ((ak >> 1) * 68 + am) * 2 + (ak & 1);
    const int ai1 = ((ak >> 1) * 68 + am + 32) * 2 + (ak & 1);
    const int wi0 = ((wk >> 1) * 68 + wn) * 2 + (wk & 1);
    const int wi1 = ((4 + (wk >> 1)) * 68 + wn) * 2 + (wk & 1);

    ull acc[2][4] = {};
    float ra0, ra1;
    if (c < 2) {
        ra0 = Ax[0]; ra1 = Ax[(size_t)32 * (Tt * Ii)];
    } else {
        const float* p0 = Ar;
        const float* p1 = Ar + (size_t)32 * Mm;
        ra0 = p0[0] + p0[BM] + p0[2 * BM] + p0[3 * BM];
        ra1 = p1[0] + p1[BM] + p1[2 * BM] + p1[3 * BM];
    }
    float rw0 = Wp[0], rw1 = Wp[(size_t)8 * Hh];
    Af[ai0] = ra0; Af[ai1] = ra1;
    Wf[wi0] = rw0; Wf[wi1] = rw1;
    __syncthreads();
    int buf = 0;
    for (int k0 = 0; k0 < 256; k0 += 16) {
        if (k0 + 16 < 256) {
            if (c < 2) {
                ra0 = Ax[k0 + 16];
                ra1 = Ax[(size_t)32 * (Tt * Ii) + k0 + 16];
            } else {
                const float* p0 = Ar + k0 + 16;
                const float* p1 = Ar + (size_t)32 * Mm + k0 + 16;
                ra0 = p0[0] + p0[BM] + p0[2 * BM] + p0[3 * BM];
                ra1 = p1[0] + p1[BM] + p1[2 * BM] + p1[3 * BM];
            }
            const float* Wp2 = Wp + (size_t)(k0 + 16) * Hh;
            rw0 = Wp2[0]; rw1 = Wp2[(size_t)8 * Hh];
        }
        const ull* Ab = Au + buf * OPB;
        const ull* Wb = Wu + buf * OPB;
        #pragma unroll
        for (int kp = 0; kp < 8; kp++) {
            ulonglong2 a2 = *(const ulonglong2*)(Ab + kp * 68 + ty * 2);
            ull w0 = Wb[kp * 68 + tx];
            ull w1 = Wb[kp * 68 + tx + 16];
            ull w2 = Wb[kp * 68 + tx + 32];
            ull w3 = Wb[kp * 68 + tx + 48];
            FMA2x4(acc, a2, w0, w1, w2, w3);
        }
        if (k0 + 16 < 256) {
            __syncthreads();
            int nb = buf ^ 1;
            Af[nb * 1088 + ai0] = ra0; Af[nb * 1088 + ai1] = ra1;
            Wf[nb * 1088 + wi0] = rw0; Wf[nb * 1088 + wi1] = rw1;
            __syncthreads();
            buf = nb;
        }
    }
    __syncthreads();
    float* C = g_hpart + (size_t)c * BH;
    #pragma unroll
    for (int r = 0; r < 2; r++) {
        int row = bm + ty * 2 + r;
        #pragma unroll
        for (int j = 0; j < 4; j++)
            C[(size_t)row * Hh + (bn + tx + j * 16)] = psum(acc[r][j]);
    }
}

// ---------------- small row-wise items ---------------------------------------
static __device__ __noinline__ void invnorm_item(int item)
{
    int w = threadIdx.x >> 5, lane = threadIdx.x & 31;
    for (int rr = w; rr < 128; rr += 16) {
        int n = item * 128 + rr;
        float s = 0.f;
        for (int c = lane; c < Mm; c += 32) {
            float v = g_mem[(size_t)n * Mm + c];
            s += v * v;
        }
        s = warpReduceSum(s);
        if (lane == 0) g_invmem[n] = 1.f / (sqrtf(s) + 1e-8f);
    }
}

static __device__ __noinline__ void scalars_item(int i)
{
    int head = i >> 3, rb = i & 7;
    const float* p = head ? g_pr : g_pw;
    float* sc = head ? g_scr : g_scw;
    int w = threadIdx.x >> 5, lane = threadIdx.x & 31;
    for (int rr = w; rr < 32; rr += 16) {
        int b = rb * 32 + rr;
        const float* row = p + (size_t)b * (Mm + 6);
        float s = 0.f;
        for (int c = lane; c < Mm; c += 32) {
            float v = row[c];
            s += v * v;
        }
        s = warpReduceSum(s);
        if (lane == 0) {
            sc[b * 8 + 0] = softplus_(row[Mm + 0]);
            sc[b * 8 + 1] = sigm(row[Mm + 1]);
            float s0 = row[Mm + 2], s1 = row[Mm + 3], s2 = row[Mm + 4];
            float mx = fmaxf(s0, fmaxf(s1, s2));
            float e0 = __expf(s0 - mx), e1 = __expf(s1 - mx), e2 = __expf(s2 - mx);
            float inv = 1.f / (e0 + e1 + e2);
            sc[b * 8 + 2] = e0 * inv;
            sc[b * 8 + 3] = e1 * inv;
            sc[b * 8 + 4] = e2 * inv;
            sc[b * 8 + 5] = 1.f + softplus_(row[Mm + 5]);
            sc[b * 8 + 6] = 1.f / (sqrtf(s) + 1e-8f);
        }
    }
}

// -------- fused address tail: softmax -> interpolate -> shift -> sharpen -----
static __device__ __noinline__ void tail_item(int it, float* shb)
{
    float* wg = shb;                  // 1024 floats
    int b = it & 255, head = it >> 8;
    const float* sim = head ? g_simr : g_simw;
    float* wv = head ? g_wr : g_ww;
    const float* sc = head ? g_scr : g_scw;
    int tid = threadIdx.x;
    float beta = sc[b * 8 + 0], g = sc[b * 8 + 1];
    float s0 = sc[b * 8 + 2], s1 = sc[b * 8 + 3], s2 = sc[b * 8 + 4];
    float gamma = sc[b * 8 + 5], invk = sc[b * 8 + 6];
    float scale = beta * invk;

    float v[2];
    float mx = -3.4e38f;
    #pragma unroll
    for (int i = 0; i < 2; i++) {
        int n = tid + i * 512;
        float t = sim[(size_t)b * Nn + n] * scale * g_invmem[n];
        v[i] = t;
        mx = fmaxf(mx, t);
    }
    mx = blockReduceMax512(mx);
    float s = 0.f;
    #pragma unroll
    for (int i = 0; i < 2; i++) { v[i] = __expf(v[i] - mx); s += v[i]; }
    s = blockReduceSum512(s);
    float invs = 1.f / s;
    #pragma unroll
    for (int i = 0; i < 2; i++) {
        int n = tid + i * 512;
        wg[n] = g * (v[i] * invs) + (1.f - g) * wv[(size_t)b * Nn + n];
    }
    __syncthreads();
    float wp[2];
    float local = 0.f;
    #pragma unroll
    for (int i = 0; i < 2; i++) {
        int n = tid + i * 512;
        float wt = s0 * wg[(n + 1) & (Nn - 1)] + s1 * wg[n] + s2 * wg[(n - 1) & (Nn - 1)];
        float pv = __powf(wt, gamma);
        wp[i] = pv;
        local += pv;
    }
    local = blockReduceSum512(local);
    float invt = 1.f / (local + 1e-8f);
    #pragma unroll
    for (int i = 0; i < 2; i++) {
        int n = tid + i * 512;
        wv[(size_t)b * Nn + n] = wp[i] * invt;
    }
    __syncthreads();
}

// ---------------- the persistent kernel --------------------------------------
__global__ void __launch_bounds__(NTHR, 1) ntm_persistent(
    const float* __restrict__ x,
    const float* __restrict__ mem0, const float* __restrict__ wr0,
    const float* __restrict__ ww0,  const float* __restrict__ h0,
    const float* __restrict__ Wx,   const float* __restrict__ Wr,
    const float* __restrict__ bh,
    const float* __restrict__ Whr,  const float* __restrict__ bhr,
    const float* __restrict__ Whw,  const float* __restrict__ bhw,
    const float* __restrict__ Wea,  const float* __restrict__ bea,
    const float* __restrict__ Wo,   const float* __restrict__ bo,
    float* __restrict__ out)
{
    // 3 operands x 2 bufs x 544 ull = 26112 bytes
    __shared__ __align__(16) float shbuf[6528];
    const int tid = threadIdx.x;
    const int gtid = blockIdx.x * NTHR + tid;
    const int gstride = NBLK * NTHR;

    // P0: init carried state
    for (int i = gtid; i < Nn * Mm; i += gstride) g_mem[i] = mem0[i];
    for (int i = gtid; i < Bb * Nn; i += gstride) { g_wr[i] = wr0[i]; g_ww[i] = ww0[i]; }
    for (int i = gtid; i < Bb * Hh; i += gstride) g_h[i] = h0[i];
    gridBarrier();

    // P1: ea from h0 (64 tiles)
    for (int it = blockIdx.x; it < 64; it += NBLK) {
        int tm = it >> 4, tn = it & 15;
        gemm64_nn(g_h, Hh, Wea, 2 * Mm, bea, g_ea, 2 * Mm,
                  tm * 64, tn * 64, 2 * Mm, Hh, 4, shbuf);
    }
    gridBarrier();

    for (int t = 0; t < Tt; t++) {
        // B: memupd (128) + out_{t-1} tiles 0..19  => exactly 148 items
        for (int it = blockIdx.x; it < 148; it += NBLK) {
            if (it < 128) memupd_tile(it >> 3, it & 7, shbuf);
            else if (t > 0) {
                int o = it - 128;                         // 0..19
                gemm64_nn(g_h, Hh, Wo, Oo, bo, out + (size_t)(t - 1) * Oo, Tt * Oo,
                          (o >> 3) * 64, (o & 7) * 64, Oo, Hh, 2, shbuf);
            }
        }
        gridBarrier();

        // C: r split-K (128) + invnorm (8) + out_{t-1} tiles 20..31 => 148
        for (int it = blockIdx.x; it < 148; it += NBLK) {
            if (it < 128) {
                int c = it >> 5, rest = it & 31, tm = rest >> 3, tn = rest & 7;
                gemm64_nn(g_wr + c * 256, Nn, g_mem + (size_t)c * 256 * Mm, Mm, nullptr,
                          g_rpart + (size_t)c * BM, Mm, tm * 64, tn * 64, Mm, 256, 0, shbuf);
            } else if (it < 136) invnorm_item(it - 128);
            else if (t > 0) {
                int o = it - 136 + 20;                    // 20..31
                gemm64_nn(g_h, Hh, Wo, Oo, bo, out + (size_t)(t - 1) * Oo, Tt * Oo,
                          (o >> 3) * 64, (o & 7) * 64, Oo, Hh, 2, shbuf);
            }
        }
        gridBarrier();

        // D: controller split-K (128)
        for (int it = blockIdx.x; it < 128; it += NBLK) {
            int c = it >> 5, rest = it & 31, tm = rest >> 3, tn = rest & 7;
            gemmD_tile(c, tm * 64, tn * 64, x + (size_t)t * Ii, Wx, Wr, shbuf);
        }
        gridBarrier();

        // D2: h = tanh(sum hpart + bh)
        for (int i = gtid; i < BH; i += gstride)
            g_h[i] = tanh_f(g_hpart[i] + g_hpart[i + BH] + g_hpart[i + 2 * BH]
                            + g_hpart[i + 3 * BH] + bh[i & 511]);
        gridBarrier();

        // E: pw(36) + pr(36) + ea-next(64) = 136 items, single round
        for (int it = blockIdx.x; it < 136; it += NBLK) {
            if (it < 36) {
                int tm = it / 9, tn = it % 9;
                gemm64_nn(g_h, Hh, Whw, Mm + 6, bhw, g_pw, Mm + 6,
                          tm * 64, tn * 64, Mm + 6, Hh, 3, shbuf);
            } else if (it < 72) {
                int i2 = it - 36, tm = i2 / 9, tn = i2 % 9;
                gemm64_nn(g_h, Hh, Whr, Mm + 6, bhr, g_pr, Mm + 6,
                          tm * 64, tn * 64, Mm + 6, Hh, 3, shbuf);
            } else {
                int i2 = it - 72, tm = i2 >> 4, tn = i2 & 15;
                gemm64_nn(g_h, Hh, Wea, 2 * Mm, bea, g_ea, 2 * Mm,
                          tm * 64, tn * 64, 2 * Mm, Hh, 4, shbuf);
            }
        }
        gridBarrier();

        // F: simw(64) simr(64) + head scalars(16) = 144
        for (int it = blockIdx.x; it < 144; it += NBLK) {
            if (it < 64) {
                int tm = it >> 4, tn = it & 15;
                gemm64_nt(g_pw, Mm + 6, g_mem, Mm, g_simw, Nn,
                          tm * 64, tn * 64, Mm, shbuf);
            } else if (it < 128) {
                int i2 = it - 64, tm = i2 >> 4, tn = i2 & 15;
                gemm64_nt(g_pr, Mm + 6, g_mem, Mm, g_simr, Nn,
                          tm * 64, tn * 64, Mm, shbuf);
            } else scalars_item(it - 128);
        }
        gridBarrier();

        // G: address tails (512 rows)
        for (int it = blockIdx.x; it < 512; it += NBLK)
            tail_item(it, shbuf);
        gridBarrier();
    }

    // final out for t = 127 (h still holds h_127)
    for (int it = blockIdx.x; it < 32; it += NBLK) {
        gemm64_nn(g_h, Hh, Wo, Oo, bo, out + (size_t)(Tt - 1) * Oo, Tt * Oo,
                  (it >> 3) * 64, (it & 7) * 64, Oo, Hh, 2, shbuf);
    }
}

// ---------------- host --------------------------------------------------------
extern "C" void kernel_launch(void* const* d_in, const int* in_sizes, int n_in,
                              void* d_out, int out_size)
{
    const float* x    = (const float*)d_in[0];
    const float* mem0 = (const float*)d_in[1];
    const float* wr0  = (const float*)d_in[2];
    const float* ww0  = (const float*)d_in[3];
    const float* h0   = (const float*)d_in[4];
    const float* Wx   = (const float*)d_in[5];
    const float* Wr   = (const float*)d_in[6];
    const float* bh   = (const float*)d_in[7];
    const float* Whr  = (const float*)d_in[8];
    const float* bhr  = (const float*)d_in[9];
    const float* Whw  = (const float*)d_in[10];
    const float* bhw  = (const float*)d_in[11];
    const float* Wea  = (const float*)d_in[12];
    const float* bea  = (const float*)d_in[13];
    const float* Wo   = (const float*)d_in[14];
    const float* bo   = (const float*)d_in[15];
    float* out = (float*)d_out;

    ntm_persistent<<<NBLK, NTHR>>>(x, mem0, wr0, ww0, h0, Wx, Wr, bh,
                                   Whr, bhr, Whw, bhw, Wea, bea, Wo, bo, out);
}